// round 2
// baseline (speedup 1.0000x reference)
#include <cuda_runtime.h>

#define B_   4
#define S_   2048
#define H_   1024
#define NH_  16
#define HD_  64
#define MTOT (B_ * S_)          // 8192

// Scratch: Q/K/V in [B, NH, S, HD] layout (32 MB each). __device__ globals are
// the sanctioned scratch mechanism (no allocations allowed in kernel_launch).
__device__ float g_q[B_ * NH_ * S_ * HD_];
__device__ float g_k[B_ * NH_ * S_ * HD_];
__device__ float g_v[B_ * NH_ * S_ * HD_];

// ---------------------------------------------------------------------------
// Kernel 1: fused QKV projection.
//   out = hidden @ W + bias + emb[index]   for W in {Wq,Wk,Wv} (blockIdx.z)
// 128x128 block tile, BK=8, 256 threads, 8x8 per-thread micro-tile.
// Epilogue writes in split-head layout [B, NH, S, HD].
// ---------------------------------------------------------------------------
__global__ __launch_bounds__(256, 2) void qkv_gemm_kernel(
    const float* __restrict__ hs,
    const float* __restrict__ Wq, const float* __restrict__ bq,
    const float* __restrict__ Wk, const float* __restrict__ bk,
    const float* __restrict__ Wv, const float* __restrict__ bv,
    const float* __restrict__ qe, const float* __restrict__ ke,
    const float* __restrict__ ve,
    const int* __restrict__ idxp)
{
    const float* W;
    const float* bias;
    const float* emb;
    float* out;
    const int z = blockIdx.z;
    if (z == 0)      { W = Wq; bias = bq; emb = qe; out = g_q; }
    else if (z == 1) { W = Wk; bias = bk; emb = ke; out = g_k; }
    else             { W = Wv; bias = bv; emb = ve; out = g_v; }
    const int idx = idxp[0];
    emb += idx * H_;

    __shared__ float As[8][128];   // A transposed: As[k][m]
    __shared__ float Bs[8][128];   // Bs[k][n]

    const int m0 = blockIdx.y * 128;
    const int n0 = blockIdx.x * 128;
    const int tid = threadIdx.x;
    const int tm = tid >> 4;       // 0..15
    const int tn = tid & 15;       // 0..15

    // global->smem load indices
    const int arow = tid >> 1;           // 0..127
    const int acol = (tid & 1) * 4;      // 0 or 4
    const int brow = tid >> 5;           // 0..7
    const int bcol = (tid & 31) * 4;     // 0..124

    float acc[8][8];
#pragma unroll
    for (int i = 0; i < 8; i++)
#pragma unroll
        for (int j = 0; j < 8; j++) acc[i][j] = 0.f;

    for (int k0 = 0; k0 < H_; k0 += 8) {
        float4 a = *(const float4*)&hs[(m0 + arow) * H_ + k0 + acol];
        As[acol + 0][arow] = a.x;
        As[acol + 1][arow] = a.y;
        As[acol + 2][arow] = a.z;
        As[acol + 3][arow] = a.w;
        *(float4*)&Bs[brow][bcol] =
            *(const float4*)&W[(k0 + brow) * H_ + n0 + bcol];
        __syncthreads();

#pragma unroll
        for (int kk = 0; kk < 8; kk++) {
            float ar[8], br[8];
            *(float4*)&ar[0] = *(const float4*)&As[kk][tm * 8];
            *(float4*)&ar[4] = *(const float4*)&As[kk][tm * 8 + 4];
            *(float4*)&br[0] = *(const float4*)&Bs[kk][tn * 8];
            *(float4*)&br[4] = *(const float4*)&Bs[kk][tn * 8 + 4];
#pragma unroll
            for (int i = 0; i < 8; i++)
#pragma unroll
                for (int j = 0; j < 8; j++) acc[i][j] += ar[i] * br[j];
        }
        __syncthreads();
    }

    // Epilogue: bias + task-embedding, write split-head layout.
#pragma unroll
    for (int i = 0; i < 8; i++) {
        const int m = m0 + tm * 8 + i;
        const int b = m >> 11;          // / S_
        const int s = m & (S_ - 1);
        const int nbase = n0 + tn * 8;  // 8 cols stay inside one head (64 | nbase)
        const int h = nbase >> 6;
        const int d = nbase & 63;
        float* dst = &out[(((b * NH_ + h) * S_) + s) * HD_ + d];
#pragma unroll
        for (int j = 0; j < 8; j++) {
            const int n = nbase + j;
            dst[j] = acc[i][j] + bias[n] + emb[n];
        }
    }
}

// ---------------------------------------------------------------------------
// Kernel 2: flash attention (fp32, online softmax).
// Grid: (S/128, B*NH). Block: 128 threads, 1 query per thread.
// K/V tiles of 64 rows in smem; per-key broadcast reads (conflict-free).
// Rescale of o[] happens only when the running max changes (~log S times).
// ---------------------------------------------------------------------------
__global__ __launch_bounds__(128) void attn_kernel(
    const float* __restrict__ mask,   // [B,1,1,S]
    float* __restrict__ out)          // [B,S,H]
{
    const int bh = blockIdx.y;        // 0..63
    const int b = bh >> 4;            // / NH_
    const int h = bh & (NH_ - 1);
    const int s = blockIdx.x * 128 + threadIdx.x;  // query index
    const int tid = threadIdx.x;

    __shared__ float ks[64 * 64];
    __shared__ float vs[64 * 64];
    __shared__ float msk[64];

    // load & pre-scale query (1/sqrt(HD) = 0.125)
    float q[64];
    {
        const float* qrow = &g_q[(bh * S_ + s) * HD_];
#pragma unroll
        for (int d = 0; d < 64; d += 4) {
            float4 t = *(const float4*)&qrow[d];
            q[d + 0] = t.x * 0.125f;
            q[d + 1] = t.y * 0.125f;
            q[d + 2] = t.z * 0.125f;
            q[d + 3] = t.w * 0.125f;
        }
    }

    float o[64];
#pragma unroll
    for (int d = 0; d < 64; d++) o[d] = 0.f;
    float mrun = -1e30f;
    float lsum = 0.f;

    const float* kbase = &g_k[bh * S_ * HD_];
    const float* vbase = &g_v[bh * S_ * HD_];
    const float* mbase = &mask[b * S_];

    for (int kt = 0; kt < S_; kt += 64) {
        // cooperative tile load: 4096 floats each, 8 float4 per thread
#pragma unroll
        for (int i = 0; i < 8; i++) {
            const int off = (i * 128 + tid) * 4;
            *(float4*)&ks[off] = *(const float4*)&kbase[kt * HD_ + off];
            *(float4*)&vs[off] = *(const float4*)&vbase[kt * HD_ + off];
        }
        if (tid < 64) msk[tid] = mbase[kt + tid];
        __syncthreads();

        for (int j = 0; j < 64; j++) {
            // score = q . k_j  (broadcast smem reads)
            const float4* kr = (const float4*)&ks[j * 64];
            float x = 0.f;
#pragma unroll
            for (int d4 = 0; d4 < 16; d4++) {
                float4 kv = kr[d4];
                x += q[d4 * 4 + 0] * kv.x + q[d4 * 4 + 1] * kv.y +
                     q[d4 * 4 + 2] * kv.z + q[d4 * 4 + 3] * kv.w;
            }
            x += msk[j];

            float p;
            if (x > mrun) {                   // rare after warmup
                const float scale = __expf(mrun - x);
                lsum *= scale;
#pragma unroll
                for (int d = 0; d < 64; d++) o[d] *= scale;
                mrun = x;
                p = 1.0f;
            } else {
                p = __expf(x - mrun);
            }
            lsum += p;

            const float4* vr = (const float4*)&vs[j * 64];
#pragma unroll
            for (int d4 = 0; d4 < 16; d4++) {
                float4 vv = vr[d4];
                o[d4 * 4 + 0] += p * vv.x;
                o[d4 * 4 + 1] += p * vv.y;
                o[d4 * 4 + 2] += p * vv.z;
                o[d4 * 4 + 3] += p * vv.w;
            }
        }
        __syncthreads();
    }

    const float inv = 1.0f / lsum;
    float* orow = &out[(b * S_ + s) * H_ + h * HD_];
#pragma unroll
    for (int d = 0; d < 64; d += 4) {
        float4 r;
        r.x = o[d + 0] * inv;
        r.y = o[d + 1] * inv;
        r.z = o[d + 2] * inv;
        r.w = o[d + 3] * inv;
        *(float4*)&orow[d] = r;
    }
}

// ---------------------------------------------------------------------------
extern "C" void kernel_launch(void* const* d_in, const int* in_sizes, int n_in,
                              void* d_out, int out_size)
{
    const float* hs   = (const float*)d_in[0];
    const float* mask = (const float*)d_in[1];
    const float* Wq   = (const float*)d_in[2];
    const float* bq   = (const float*)d_in[3];
    const float* Wk   = (const float*)d_in[4];
    const float* bk   = (const float*)d_in[5];
    const float* Wv   = (const float*)d_in[6];
    const float* bv   = (const float*)d_in[7];
    const float* qe   = (const float*)d_in[8];
    const float* ke   = (const float*)d_in[9];
    const float* ve   = (const float*)d_in[10];
    const int*   idx  = (const int*)d_in[11];
    float* out = (float*)d_out;

    dim3 g1(H_ / 128, MTOT / 128, 3);     // (8, 64, 3)
    qkv_gemm_kernel<<<g1, 256>>>(hs, Wq, bq, Wk, bk, Wv, bv, qe, ke, ve, idx);

    dim3 g2(S_ / 128, B_ * NH_);          // (16, 64)
    attn_kernel<<<g2, 128>>>(mask, out);
}

// round 4
// speedup vs baseline: 2.8010x; 2.8010x over previous
#include <cuda_runtime.h>
#include <cuda_fp16.h>
#include <cstdint>

#define B_   4
#define S_   2048
#define H_   1024
#define NH_  16
#define HD_  64
#define MTOT (B_ * S_)          // 8192
#define HSN  (MTOT * H_)        // 8388608

// ---------------- scratch (device globals; no allocations allowed) ----------
__device__ __half g_hsh[HSN];            // hidden states fp16 hi
__device__ __half g_hsl[HSN];            // hidden states fp16 lo (residual)
__device__ __half g_wth[3 * H_ * H_];    // W^T fp16 hi  (Wt[n*H+k] = W[k*H+n])
__device__ __half g_wtl[3 * H_ * H_];    // W^T fp16 lo
// Q/K/V in split-head layout [B, NH, S, HD], fp16 hi/lo pairs
__device__ __half g_qh[B_ * NH_ * S_ * HD_];
__device__ __half g_ql[B_ * NH_ * S_ * HD_];
__device__ __half g_kh[B_ * NH_ * S_ * HD_];
__device__ __half g_kl[B_ * NH_ * S_ * HD_];
__device__ __half g_vh[B_ * NH_ * S_ * HD_];
__device__ __half g_vl[B_ * NH_ * S_ * HD_];

// ---------------- mma / ldmatrix helpers (sm_80+ path, no tcgen05) ---------
__device__ __forceinline__ uint32_t smem_u32(const void* p) {
    uint32_t a;
    asm("{ .reg .u64 t; cvta.to.shared.u64 t, %1; cvt.u32.u64 %0, t; }"
        : "=r"(a) : "l"(p));
    return a;
}
__device__ __forceinline__ void mma16816(float* c, const uint32_t* a,
                                         uint32_t b0, uint32_t b1) {
    asm volatile(
        "mma.sync.aligned.m16n8k16.row.col.f32.f16.f16.f32 "
        "{%0,%1,%2,%3}, {%4,%5,%6,%7}, {%8,%9}, {%0,%1,%2,%3};"
        : "+f"(c[0]), "+f"(c[1]), "+f"(c[2]), "+f"(c[3])
        : "r"(a[0]), "r"(a[1]), "r"(a[2]), "r"(a[3]), "r"(b0), "r"(b1));
}
__device__ __forceinline__ void ldsm4(uint32_t* r, uint32_t addr) {
    asm volatile("ldmatrix.sync.aligned.m8n8.x4.shared.b16 {%0,%1,%2,%3}, [%4];"
                 : "=r"(r[0]), "=r"(r[1]), "=r"(r[2]), "=r"(r[3]) : "r"(addr));
}
__device__ __forceinline__ void ldsm4t(uint32_t* r, uint32_t addr) {
    asm volatile("ldmatrix.sync.aligned.m8n8.x4.trans.shared.b16 {%0,%1,%2,%3}, [%4];"
                 : "=r"(r[0]), "=r"(r[1]), "=r"(r[2]), "=r"(r[3]) : "r"(addr));
}
__device__ __forceinline__ uint32_t pack2(float x, float y) {
    __half2 h = __floats2half2_rn(x, y);
    return *(uint32_t*)&h;
}

// ---------------- prep kernels ---------------------------------------------
__global__ void convert_hs_kernel(const float* __restrict__ hs) {
    const int n4 = HSN / 4;
    for (int i = blockIdx.x * blockDim.x + threadIdx.x; i < n4;
         i += gridDim.x * blockDim.x) {
        float4 v = ((const float4*)hs)[i];
        __half h0 = __float2half_rn(v.x), h1 = __float2half_rn(v.y);
        __half h2 = __float2half_rn(v.z), h3 = __float2half_rn(v.w);
        __half l0 = __float2half_rn(v.x - __half2float(h0));
        __half l1 = __float2half_rn(v.y - __half2float(h1));
        __half l2 = __float2half_rn(v.z - __half2float(h2));
        __half l3 = __float2half_rn(v.w - __half2float(h3));
        ((__half2*)g_hsh)[2 * i]     = __halves2half2(h0, h1);
        ((__half2*)g_hsh)[2 * i + 1] = __halves2half2(h2, h3);
        ((__half2*)g_hsl)[2 * i]     = __halves2half2(l0, l1);
        ((__half2*)g_hsl)[2 * i + 1] = __halves2half2(l2, l3);
    }
}

__global__ void transpose_w_kernel(const float* __restrict__ Wq,
                                   const float* __restrict__ Wk,
                                   const float* __restrict__ Wv) {
    __shared__ float tile[32][33];
    const int z = blockIdx.z;
    const float* W = (z == 0) ? Wq : (z == 1) ? Wk : Wv;
    __half* oh = g_wth + (size_t)z * H_ * H_;
    __half* ol = g_wtl + (size_t)z * H_ * H_;

    const int x = blockIdx.x * 32 + threadIdx.x;   // col n in W
    const int y0 = blockIdx.y * 32;                // row k base
#pragma unroll
    for (int j = 0; j < 4; j++)
        tile[threadIdx.y + j * 8][threadIdx.x] =
            W[(size_t)(y0 + threadIdx.y + j * 8) * H_ + x];
    __syncthreads();
#pragma unroll
    for (int j = 0; j < 4; j++) {
        const float v = tile[threadIdx.x][threadIdx.y + j * 8];
        const int n = blockIdx.x * 32 + threadIdx.y + j * 8;
        const int k = y0 + threadIdx.x;
        __half h = __float2half_rn(v);
        oh[(size_t)n * H_ + k] = h;
        ol[(size_t)n * H_ + k] = __float2half_rn(v - __half2float(h));
    }
}

// ---------------- QKV GEMM via mma.sync (fp16 3-term split) -----------------
// CTA: 128x128 tile, 256 thr / 8 warps (4x2), warp tile 32x64, BK=32.
// Epilogue: + bias + emb, write fp16 hi/lo split-head layout.
#define GLD 40   // smem leading dim (halves) for 32-wide k panel

__global__ __launch_bounds__(256) void qkv_mma_kernel(
    const float* __restrict__ bq, const float* __restrict__ bk,
    const float* __restrict__ bv,
    const float* __restrict__ qe, const float* __restrict__ ke,
    const float* __restrict__ ve,
    const int* __restrict__ idxp)
{
    __shared__ __half Ah[128 * GLD], Al[128 * GLD];
    __shared__ __half Bh[128 * GLD], Bl[128 * GLD];
    __shared__ float be[128];

    const int tid = threadIdx.x;
    const int wid = tid >> 5;
    const int lane = tid & 31;
    const int z = blockIdx.z;

    const float* bias;
    const float* emb;
    __half *ohp, *olp;
    if (z == 0)      { bias = bq; emb = qe; ohp = g_qh; olp = g_ql; }
    else if (z == 1) { bias = bk; emb = ke; ohp = g_kh; olp = g_kl; }
    else             { bias = bv; emb = ve; ohp = g_vh; olp = g_vl; }
    emb += (size_t)idxp[0] * H_;

    const int m0 = blockIdx.y * 128;
    const int n0 = blockIdx.x * 128;

    if (tid < 128) be[tid] = bias[n0 + tid] + emb[n0 + tid];

    const int wm = wid & 3;           // 0..3 (rows)
    const int wn = wid >> 2;          // 0..1 (cols)

    // gmem load mapping: thread -> row tid>>1, two 16B chunks
    const int lrow = tid >> 1;
    const int c0 = (tid & 1) * 2;
    const size_t gA = (size_t)(m0 + lrow) * H_;
    const size_t gB = (size_t)(n0 + lrow) * H_;
    uint4* sAh = (uint4*)(Ah + lrow * GLD);
    uint4* sAl = (uint4*)(Al + lrow * GLD);
    uint4* sBh = (uint4*)(Bh + lrow * GLD);
    uint4* sBl = (uint4*)(Bl + lrow * GLD);

    // ldmatrix base addresses
    const uint32_t lrow16 = (lane & 15);
    const uint32_t lcol8  = (lane >> 4) * 8;
    const uint32_t aBaseH = smem_u32(Ah) + ((wm * 32 + lrow16) * GLD + lcol8) * 2;
    const uint32_t aBaseL = smem_u32(Al) + ((wm * 32 + lrow16) * GLD + lcol8) * 2;
    const uint32_t bBaseH = smem_u32(Bh) + ((wn * 64 + lrow16) * GLD + lcol8) * 2;
    const uint32_t bBaseL = smem_u32(Bl) + ((wn * 64 + lrow16) * GLD + lcol8) * 2;

    float c[2][8][4];
#pragma unroll
    for (int i = 0; i < 2; i++)
#pragma unroll
        for (int j = 0; j < 8; j++)
#pragma unroll
            for (int q = 0; q < 4; q++) c[i][j][q] = 0.f;

    for (int kt = 0; kt < 32; kt++) {
        const int k0 = kt * 32;
        const uint4* pAh = (const uint4*)(g_hsh + gA + k0);
        const uint4* pAl = (const uint4*)(g_hsl + gA + k0);
        const uint4* pBh = (const uint4*)(g_wth + (size_t)z * H_ * H_ + gB + k0);
        const uint4* pBl = (const uint4*)(g_wtl + (size_t)z * H_ * H_ + gB + k0);
        sAh[c0] = pAh[c0]; sAh[c0 + 1] = pAh[c0 + 1];
        sAl[c0] = pAl[c0]; sAl[c0 + 1] = pAl[c0 + 1];
        sBh[c0] = pBh[c0]; sBh[c0 + 1] = pBh[c0 + 1];
        sBl[c0] = pBl[c0]; sBl[c0 + 1] = pBl[c0 + 1];
        __syncthreads();

#pragma unroll
        for (int k16 = 0; k16 < 2; k16++) {
            const uint32_t koff = k16 * 32;   // 16 halves
            uint32_t ah[2][4], al[2][4];
#pragma unroll
            for (int mt = 0; mt < 2; mt++) {
                ldsm4(ah[mt], aBaseH + mt * (16 * GLD * 2) + koff);
                ldsm4(al[mt], aBaseL + mt * (16 * GLD * 2) + koff);
            }
#pragma unroll
            for (int ng = 0; ng < 4; ng++) {
                uint32_t bh[4], bl[4];
                ldsm4(bh, bBaseH + ng * (16 * GLD * 2) + koff);
                ldsm4(bl, bBaseL + ng * (16 * GLD * 2) + koff);
#pragma unroll
                for (int mt = 0; mt < 2; mt++) {
                    mma16816(c[mt][2 * ng],     ah[mt], bh[0], bh[2]);
                    mma16816(c[mt][2 * ng],     ah[mt], bl[0], bl[2]);
                    mma16816(c[mt][2 * ng],     al[mt], bh[0], bh[2]);
                    mma16816(c[mt][2 * ng + 1], ah[mt], bh[1], bh[3]);
                    mma16816(c[mt][2 * ng + 1], ah[mt], bl[1], bl[3]);
                    mma16816(c[mt][2 * ng + 1], al[mt], bh[1], bh[3]);
                }
            }
        }
        __syncthreads();
    }

    // Epilogue
#pragma unroll
    for (int mt = 0; mt < 2; mt++) {
#pragma unroll
        for (int nt = 0; nt < 8; nt++) {
            const int mloc = wm * 32 + mt * 16 + (lane >> 2);
            const int nloc = wn * 64 + nt * 8 + (lane & 3) * 2;
            const float v00 = c[mt][nt][0] + be[nloc];
            const float v01 = c[mt][nt][1] + be[nloc + 1];
            const float v10 = c[mt][nt][2] + be[nloc];
            const float v11 = c[mt][nt][3] + be[nloc + 1];
            const int N = n0 + nloc;
            const int head = N >> 6;
            const int d = N & 63;
            const int m = m0 + mloc;
            const int bb = m >> 11;
            const int s = m & (S_ - 1);
            const size_t i0 = (((size_t)(bb * NH_ + head)) * S_ + s) * HD_ + d;
            const size_t i1 = (((size_t)(bb * NH_ + head)) * S_ + s + 8) * HD_ + d;
            __half h00 = __float2half_rn(v00), h01 = __float2half_rn(v01);
            __half h10 = __float2half_rn(v10), h11 = __float2half_rn(v11);
            *(__half2*)&ohp[i0] = __halves2half2(h00, h01);
            *(__half2*)&ohp[i1] = __halves2half2(h10, h11);
            *(__half2*)&olp[i0] = __halves2half2(
                __float2half_rn(v00 - __half2float(h00)),
                __float2half_rn(v01 - __half2float(h01)));
            *(__half2*)&olp[i1] = __halves2half2(
                __float2half_rn(v10 - __half2float(h10)),
                __float2half_rn(v11 - __half2float(h11)));
        }
    }
}

// ---------------- flash attention via mma.sync ------------------------------
// Block: 256 thr / 8 warps, 128 queries (16 per warp), K/V tiles of 64.
// Scores: 3-term fp16 split QK^T. Softmax in c-frag registers (quad shfl).
// PV: P split hi/lo (c-frag -> a-frag identity), V via ldmatrix.trans.
#define KLD 72   // smem leading dim (halves) for 64-wide tiles

__global__ __launch_bounds__(256) void attn_mma_kernel(
    const float* __restrict__ mask,   // [B,1,1,S]
    float* __restrict__ out)          // [B,S,H]
{
    __shared__ __half kh[64 * KLD], kl[64 * KLD];
    __shared__ __half vh[64 * KLD], vl[64 * KLD];
    __shared__ float msk[64];

    const int tid = threadIdx.x;
    const int wid = tid >> 5;
    const int lane = tid & 31;
    const int bh = blockIdx.y;
    const int b = bh >> 4;
    const int h = bh & (NH_ - 1);
    const int q0 = blockIdx.x * 128 + wid * 16;

    const int r = lane >> 2;
    const int cc = (lane & 3) * 2;

    // Q fragments (hi/lo) loaded directly from gmem in a-frag layout
    uint32_t qhf[4][4], qlf[4][4];
    {
        const __half* qb_h = g_qh + ((size_t)bh * S_ + q0) * HD_;
        const __half* qb_l = g_ql + ((size_t)bh * S_ + q0) * HD_;
#pragma unroll
        for (int dc = 0; dc < 4; dc++) {
            const int o00 = (r)     * HD_ + dc * 16 + cc;
            const int o10 = (r + 8) * HD_ + dc * 16 + cc;
            qhf[dc][0] = *(const uint32_t*)&qb_h[o00];
            qhf[dc][1] = *(const uint32_t*)&qb_h[o10];
            qhf[dc][2] = *(const uint32_t*)&qb_h[o00 + 8];
            qhf[dc][3] = *(const uint32_t*)&qb_h[o10 + 8];
            qlf[dc][0] = *(const uint32_t*)&qb_l[o00];
            qlf[dc][1] = *(const uint32_t*)&qb_l[o10];
            qlf[dc][2] = *(const uint32_t*)&qb_l[o00 + 8];
            qlf[dc][3] = *(const uint32_t*)&qb_l[o10 + 8];
        }
    }

    float o[8][4];
#pragma unroll
    for (int t = 0; t < 8; t++)
#pragma unroll
        for (int q = 0; q < 4; q++) o[t][q] = 0.f;
    float mrow0 = -1e30f, mrow1 = -1e30f;
    float lrow0 = 0.f, lrow1 = 0.f;

    // smem ldmatrix bases (row pattern identical for all 4 arrays)
    const uint32_t lmOff = ((lane & 15) * KLD + (lane >> 4) * 8) * 2;
    const uint32_t khB = smem_u32(kh) + lmOff;
    const uint32_t klB = smem_u32(kl) + lmOff;
    const uint32_t vhB = smem_u32(vh) + lmOff;
    const uint32_t vlB = smem_u32(vl) + lmOff;

    // tile load mapping: thread -> row tid>>2, chunks (tid&3)*2 + {0,1}
    const int trow = tid >> 2;
    const int tch = (tid & 3) * 2;
    uint4* skh = (uint4*)(kh + trow * KLD);
    uint4* skl = (uint4*)(kl + trow * KLD);
    uint4* svh = (uint4*)(vh + trow * KLD);
    uint4* svl = (uint4*)(vl + trow * KLD);

    const size_t kvrow = ((size_t)bh * S_ + trow) * HD_;
    const float* mbase = &mask[(size_t)b * S_];

    for (int kt = 0; kt < 32; kt++) {
        {
            const size_t off = kvrow + (size_t)kt * 64 * HD_;
            const uint4* pkh = (const uint4*)(g_kh + off);
            const uint4* pkl = (const uint4*)(g_kl + off);
            const uint4* pvh = (const uint4*)(g_vh + off);
            const uint4* pvl = (const uint4*)(g_vl + off);
            skh[tch] = pkh[tch]; skh[tch + 1] = pkh[tch + 1];
            skl[tch] = pkl[tch]; skl[tch + 1] = pkl[tch + 1];
            svh[tch] = pvh[tch]; svh[tch + 1] = pvh[tch + 1];
            svl[tch] = pvl[tch]; svl[tch + 1] = pvl[tch + 1];
            if (tid < 64) msk[tid] = mbase[kt * 64 + tid];
        }
        __syncthreads();

        // ---- scores ----
        float c[8][4];
#pragma unroll
        for (int t = 0; t < 8; t++)
#pragma unroll
            for (int q = 0; q < 4; q++) c[t][q] = 0.f;

#pragma unroll
        for (int kg = 0; kg < 4; kg++) {
#pragma unroll
            for (int dc = 0; dc < 4; dc++) {
                const uint32_t off = (kg * 16 * KLD + dc * 16) * 2;
                uint32_t kf[4], lf[4];
                ldsm4(kf, khB + off);
                ldsm4(lf, klB + off);
                mma16816(c[2 * kg],     qhf[dc], kf[0], kf[2]);
                mma16816(c[2 * kg],     qhf[dc], lf[0], lf[2]);
                mma16816(c[2 * kg],     qlf[dc], kf[0], kf[2]);
                mma16816(c[2 * kg + 1], qhf[dc], kf[1], kf[3]);
                mma16816(c[2 * kg + 1], qhf[dc], lf[1], lf[3]);
                mma16816(c[2 * kg + 1], qlf[dc], kf[1], kf[3]);
            }
        }

        // ---- softmax (rows r, r+8 per lane; quad holds full 64-col rows) ----
        float mx0 = mrow0, mx1 = mrow1;
#pragma unroll
        for (int t = 0; t < 8; t++) {
            const float mk0 = msk[8 * t + cc];
            const float mk1 = msk[8 * t + cc + 1];
            c[t][0] = c[t][0] * 0.125f + mk0;
            c[t][1] = c[t][1] * 0.125f + mk1;
            c[t][2] = c[t][2] * 0.125f + mk0;
            c[t][3] = c[t][3] * 0.125f + mk1;
            mx0 = fmaxf(mx0, fmaxf(c[t][0], c[t][1]));
            mx1 = fmaxf(mx1, fmaxf(c[t][2], c[t][3]));
        }
        mx0 = fmaxf(mx0, __shfl_xor_sync(0xffffffffu, mx0, 1));
        mx0 = fmaxf(mx0, __shfl_xor_sync(0xffffffffu, mx0, 2));
        mx1 = fmaxf(mx1, __shfl_xor_sync(0xffffffffu, mx1, 1));
        mx1 = fmaxf(mx1, __shfl_xor_sync(0xffffffffu, mx1, 2));

        const float sc0 = __expf(mrow0 - mx0);
        const float sc1 = __expf(mrow1 - mx1);
        mrow0 = mx0; mrow1 = mx1;
        lrow0 *= sc0; lrow1 *= sc1;
        float rs0 = 0.f, rs1 = 0.f;
#pragma unroll
        for (int t = 0; t < 8; t++) {
            c[t][0] = __expf(c[t][0] - mx0);
            c[t][1] = __expf(c[t][1] - mx0);
            c[t][2] = __expf(c[t][2] - mx1);
            c[t][3] = __expf(c[t][3] - mx1);
            rs0 += c[t][0] + c[t][1];
            rs1 += c[t][2] + c[t][3];
        }
        rs0 += __shfl_xor_sync(0xffffffffu, rs0, 1);
        rs0 += __shfl_xor_sync(0xffffffffu, rs0, 2);
        rs1 += __shfl_xor_sync(0xffffffffu, rs1, 1);
        rs1 += __shfl_xor_sync(0xffffffffu, rs1, 2);
        lrow0 += rs0; lrow1 += rs1;
#pragma unroll
        for (int t = 0; t < 8; t++) {
            o[t][0] *= sc0; o[t][1] *= sc0;
            o[t][2] *= sc1; o[t][3] *= sc1;
        }

        // ---- PV ----
#pragma unroll
        for (int kg = 0; kg < 4; kg++) {
            // P hi/lo a-frags from c-frag pairs (n-tiles 2kg, 2kg+1)
            uint32_t aph[4], apl[4];
            {
                const float p0 = c[2 * kg][0], p1 = c[2 * kg][1];
                const float p2 = c[2 * kg][2], p3 = c[2 * kg][3];
                const float p4 = c[2 * kg + 1][0], p5 = c[2 * kg + 1][1];
                const float p6 = c[2 * kg + 1][2], p7 = c[2 * kg + 1][3];
                __half h0 = __float2half_rn(p0), h1 = __float2half_rn(p1);
                __half h2 = __float2half_rn(p2), h3 = __float2half_rn(p3);
                __half h4 = __float2half_rn(p4), h5 = __float2half_rn(p5);
                __half h6 = __float2half_rn(p6), h7 = __float2half_rn(p7);
                __half2 t0 = __halves2half2(h0, h1); aph[0] = *(uint32_t*)&t0;
                __half2 t1 = __halves2half2(h2, h3); aph[1] = *(uint32_t*)&t1;
                __half2 t2 = __halves2half2(h4, h5); aph[2] = *(uint32_t*)&t2;
                __half2 t3 = __halves2half2(h6, h7); aph[3] = *(uint32_t*)&t3;
                apl[0] = pack2(p0 - __half2float(h0), p1 - __half2float(h1));
                apl[1] = pack2(p2 - __half2float(h2), p3 - __half2float(h3));
                apl[2] = pack2(p4 - __half2float(h4), p5 - __half2float(h5));
                apl[3] = pack2(p6 - __half2float(h6), p7 - __half2float(h7));
            }
#pragma unroll
            for (int hc = 0; hc < 4; hc++) {
                const uint32_t off = (kg * 16 * KLD + hc * 16) * 2;
                uint32_t vf[4], wf[4];
                ldsm4t(vf, vhB + off);
                ldsm4t(wf, vlB + off);
                mma16816(o[2 * hc],     aph, vf[0], vf[1]);
                mma16816(o[2 * hc],     aph, wf[0], wf[1]);
                mma16816(o[2 * hc],     apl, vf[0], vf[1]);
                mma16816(o[2 * hc + 1], aph, vf[2], vf[3]);
                mma16816(o[2 * hc + 1], aph, wf[2], wf[3]);
                mma16816(o[2 * hc + 1], apl, vf[2], vf[3]);
            }
        }
        __syncthreads();
    }

    // ---- normalize + write ----
    const float inv0 = 1.0f / lrow0;
    const float inv1 = 1.0f / lrow1;
    const int srow = q0 + r;
    float* ob0 = out + ((size_t)b * S_ + srow) * H_ + h * HD_;
    float* ob1 = out + ((size_t)b * S_ + srow + 8) * H_ + h * HD_;
#pragma unroll
    for (int t = 0; t < 8; t++) {
        float2 w0, w1;
        w0.x = o[t][0] * inv0; w0.y = o[t][1] * inv0;
        w1.x = o[t][2] * inv1; w1.y = o[t][3] * inv1;
        *(float2*)&ob0[8 * t + cc] = w0;
        *(float2*)&ob1[8 * t + cc] = w1;
    }
}

// ---------------------------------------------------------------------------
extern "C" void kernel_launch(void* const* d_in, const int* in_sizes, int n_in,
                              void* d_out, int out_size)
{
    const float* hs   = (const float*)d_in[0];
    const float* mask = (const float*)d_in[1];
    const float* Wq   = (const float*)d_in[2];
    const float* bq   = (const float*)d_in[3];
    const float* Wk   = (const float*)d_in[4];
    const float* bk   = (const float*)d_in[5];
    const float* Wv   = (const float*)d_in[6];
    const float* bv   = (const float*)d_in[7];
    const float* qe   = (const float*)d_in[8];
    const float* ke   = (const float*)d_in[9];
    const float* ve   = (const float*)d_in[10];
    const int*   idx  = (const int*)d_in[11];
    float* out = (float*)d_out;

    convert_hs_kernel<<<2048, 256>>>(hs);
    transpose_w_kernel<<<dim3(32, 32, 3), dim3(32, 8)>>>(Wq, Wk, Wv);
    qkv_mma_kernel<<<dim3(8, 64, 3), 256>>>(bq, bk, bv, qe, ke, ve, idx);
    attn_mma_kernel<<<dim3(16, 64), 256>>>(mask, out);
}

// round 5
// speedup vs baseline: 3.0391x; 1.0850x over previous
#include <cuda_runtime.h>
#include <cuda_fp16.h>
#include <cstdint>

#define B_   4
#define S_   2048
#define H_   1024
#define NH_  16
#define HD_  64
#define MTOT (B_ * S_)          // 8192
#define HSN  (MTOT * H_)        // 8388608

// ---------------- scratch (device globals; no allocations allowed) ----------
__device__ __half g_hsh[HSN];            // hidden states fp16 hi
__device__ __half g_hsl[HSN];            // hidden states fp16 lo (residual)
__device__ __half g_wth[3 * H_ * H_];    // W^T fp16 hi  (Wt[n*H+k] = W[k*H+n])
__device__ __half g_wtl[3 * H_ * H_];    // W^T fp16 lo
// Q/K/V in split-head layout [B, NH, S, HD], fp16 hi/lo pairs
__device__ __half g_qh[B_ * NH_ * S_ * HD_];
__device__ __half g_ql[B_ * NH_ * S_ * HD_];
__device__ __half g_kh[B_ * NH_ * S_ * HD_];
__device__ __half g_kl[B_ * NH_ * S_ * HD_];
__device__ __half g_vh[B_ * NH_ * S_ * HD_];
__device__ __half g_vl[B_ * NH_ * S_ * HD_];

// ---------------- helpers ---------------------------------------------------
__device__ __forceinline__ uint32_t smem_u32(const void* p) {
    uint32_t a;
    asm("{ .reg .u64 t; cvta.to.shared.u64 t, %1; cvt.u32.u64 %0, t; }"
        : "=r"(a) : "l"(p));
    return a;
}
__device__ __forceinline__ void mma16816(float* c, const uint32_t* a,
                                         uint32_t b0, uint32_t b1) {
    asm volatile(
        "mma.sync.aligned.m16n8k16.row.col.f32.f16.f16.f32 "
        "{%0,%1,%2,%3}, {%4,%5,%6,%7}, {%8,%9}, {%0,%1,%2,%3};"
        : "+f"(c[0]), "+f"(c[1]), "+f"(c[2]), "+f"(c[3])
        : "r"(a[0]), "r"(a[1]), "r"(a[2]), "r"(a[3]), "r"(b0), "r"(b1));
}
__device__ __forceinline__ void ldsm4(uint32_t* r, uint32_t addr) {
    asm volatile("ldmatrix.sync.aligned.m8n8.x4.shared.b16 {%0,%1,%2,%3}, [%4];"
                 : "=r"(r[0]), "=r"(r[1]), "=r"(r[2]), "=r"(r[3]) : "r"(addr));
}
__device__ __forceinline__ void ldsm4t(uint32_t* r, uint32_t addr) {
    asm volatile("ldmatrix.sync.aligned.m8n8.x4.trans.shared.b16 {%0,%1,%2,%3}, [%4];"
                 : "=r"(r[0]), "=r"(r[1]), "=r"(r[2]), "=r"(r[3]) : "r"(addr));
}
__device__ __forceinline__ void cp16(uint32_t dst, const void* src) {
    asm volatile("cp.async.cg.shared.global [%0], [%1], 16;"
                 :: "r"(dst), "l"(src) : "memory");
}
#define CP_COMMIT() asm volatile("cp.async.commit_group;" ::: "memory")
#define CP_WAIT1()  asm volatile("cp.async.wait_group 1;" ::: "memory")
#define CP_WAIT0()  asm volatile("cp.async.wait_group 0;" ::: "memory")

// ---------------- prep kernels ---------------------------------------------
__global__ void convert_hs_kernel(const float* __restrict__ hs) {
    const int n4 = HSN / 4;
    for (int i = blockIdx.x * blockDim.x + threadIdx.x; i < n4;
         i += gridDim.x * blockDim.x) {
        float4 v = ((const float4*)hs)[i];
        __half h0 = __float2half_rn(v.x), h1 = __float2half_rn(v.y);
        __half h2 = __float2half_rn(v.z), h3 = __float2half_rn(v.w);
        __half l0 = __float2half_rn(v.x - __half2float(h0));
        __half l1 = __float2half_rn(v.y - __half2float(h1));
        __half l2 = __float2half_rn(v.z - __half2float(h2));
        __half l3 = __float2half_rn(v.w - __half2float(h3));
        ((__half2*)g_hsh)[2 * i]     = __halves2half2(h0, h1);
        ((__half2*)g_hsh)[2 * i + 1] = __halves2half2(h2, h3);
        ((__half2*)g_hsl)[2 * i]     = __halves2half2(l0, l1);
        ((__half2*)g_hsl)[2 * i + 1] = __halves2half2(l2, l3);
    }
}

__global__ void transpose_w_kernel(const float* __restrict__ Wq,
                                   const float* __restrict__ Wk,
                                   const float* __restrict__ Wv) {
    __shared__ float tile[32][33];
    const int z = blockIdx.z;
    const float* W = (z == 0) ? Wq : (z == 1) ? Wk : Wv;
    __half* oh = g_wth + (size_t)z * H_ * H_;
    __half* ol = g_wtl + (size_t)z * H_ * H_;

    const int x = blockIdx.x * 32 + threadIdx.x;
    const int y0 = blockIdx.y * 32;
#pragma unroll
    for (int j = 0; j < 4; j++)
        tile[threadIdx.y + j * 8][threadIdx.x] =
            W[(size_t)(y0 + threadIdx.y + j * 8) * H_ + x];
    __syncthreads();
#pragma unroll
    for (int j = 0; j < 4; j++) {
        const float v = tile[threadIdx.x][threadIdx.y + j * 8];
        const int n = blockIdx.x * 32 + threadIdx.y + j * 8;
        const int k = y0 + threadIdx.x;
        __half h = __float2half_rn(v);
        oh[(size_t)n * H_ + k] = h;
        ol[(size_t)n * H_ + k] = __float2half_rn(v - __half2float(h));
    }
}

// ---------------- QKV GEMM via mma.sync, cp.async 2-stage -------------------
// CTA: 128x128 tile, 256 thr / 8 warps (4x2), warp tile 32x64, BK=32.
#define GLD   40                 // smem leading dim (halves); row = 80 B
#define QAB   (128 * GLD * 2)    // bytes per array per stage (10240)
#define QSTG  (4 * QAB)          // stage stride (40960)
#define QSM   (2 * QSTG + 512)   // + be[128]

__global__ __launch_bounds__(256) void qkv_mma_kernel(
    const float* __restrict__ bq, const float* __restrict__ bk,
    const float* __restrict__ bv,
    const float* __restrict__ qe, const float* __restrict__ ke,
    const float* __restrict__ ve,
    const int* __restrict__ idxp)
{
    extern __shared__ char smem[];
    float* be = (float*)(smem + 2 * QSTG);

    const int tid = threadIdx.x;
    const int wid = tid >> 5;
    const int lane = tid & 31;
    const int z = blockIdx.z;

    const float* bias;
    const float* emb;
    __half *ohp, *olp;
    if (z == 0)      { bias = bq; emb = qe; ohp = g_qh; olp = g_ql; }
    else if (z == 1) { bias = bk; emb = ke; ohp = g_kh; olp = g_kl; }
    else             { bias = bv; emb = ve; ohp = g_vh; olp = g_vl; }
    emb += (size_t)idxp[0] * H_;

    const int m0 = blockIdx.y * 128;
    const int n0 = blockIdx.x * 128;
    if (tid < 128) be[tid] = bias[n0 + tid] + emb[n0 + tid];

    const int wm = wid & 3;
    const int wn = wid >> 2;

    // gmem->smem mapping: thread -> row tid>>1, chunks c0, c0+1 of 4 per row
    const int lrow = tid >> 1;
    const int c0 = (tid & 1) * 2;
    const size_t gA = (size_t)(m0 + lrow) * H_;
    const size_t gB = (size_t)(n0 + lrow) * H_;
    const __half* pWh = g_wth + (size_t)z * H_ * H_;
    const __half* pWl = g_wtl + (size_t)z * H_ * H_;

    const uint32_t sbase = smem_u32(smem);
    const uint32_t rowoff = lrow * (GLD * 2) + c0 * 16;

    // ldmatrix bases
    const uint32_t lmA = ((wm * 32 + (lane & 15)) * GLD + (lane >> 4) * 8) * 2;
    const uint32_t lmB = ((wn * 64 + (lane & 15)) * GLD + (lane >> 4) * 8) * 2;

    float c[2][8][4];
#pragma unroll
    for (int i = 0; i < 2; i++)
#pragma unroll
        for (int j = 0; j < 8; j++)
#pragma unroll
            for (int q = 0; q < 4; q++) c[i][j][q] = 0.f;

    auto prefetch = [&](int kt, int stg) {
        const int k0 = kt * 32;
        const uint32_t d = sbase + stg * QSTG + rowoff;
        cp16(d,            g_hsh + gA + k0 + c0 * 8);
        cp16(d + 16,       g_hsh + gA + k0 + c0 * 8 + 8);
        cp16(d + QAB,      g_hsl + gA + k0 + c0 * 8);
        cp16(d + QAB + 16, g_hsl + gA + k0 + c0 * 8 + 8);
        cp16(d + 2 * QAB,      pWh + gB + k0 + c0 * 8);
        cp16(d + 2 * QAB + 16, pWh + gB + k0 + c0 * 8 + 8);
        cp16(d + 3 * QAB,      pWl + gB + k0 + c0 * 8);
        cp16(d + 3 * QAB + 16, pWl + gB + k0 + c0 * 8 + 8);
        CP_COMMIT();
    };

    prefetch(0, 0);
    for (int kt = 0; kt < 32; kt++) {
        const int stg = kt & 1;
        if (kt + 1 < 32) { prefetch(kt + 1, stg ^ 1); CP_WAIT1(); }
        else             { CP_WAIT0(); }
        __syncthreads();

        const uint32_t aH = sbase + stg * QSTG + lmA;
        const uint32_t aL = aH + QAB;
        const uint32_t bH = sbase + stg * QSTG + 2 * QAB + lmB;
        const uint32_t bL = bH + QAB;

#pragma unroll
        for (int k16 = 0; k16 < 2; k16++) {
            const uint32_t koff = k16 * 32;
            uint32_t ah[2][4], al[2][4];
#pragma unroll
            for (int mt = 0; mt < 2; mt++) {
                ldsm4(ah[mt], aH + mt * (16 * GLD * 2) + koff);
                ldsm4(al[mt], aL + mt * (16 * GLD * 2) + koff);
            }
#pragma unroll
            for (int ng = 0; ng < 4; ng++) {
                uint32_t bh[4], bl[4];
                ldsm4(bh, bH + ng * (16 * GLD * 2) + koff);
                ldsm4(bl, bL + ng * (16 * GLD * 2) + koff);
#pragma unroll
                for (int mt = 0; mt < 2; mt++) {
                    mma16816(c[mt][2 * ng],     ah[mt], bh[0], bh[2]);
                    mma16816(c[mt][2 * ng],     ah[mt], bl[0], bl[2]);
                    mma16816(c[mt][2 * ng],     al[mt], bh[0], bh[2]);
                    mma16816(c[mt][2 * ng + 1], ah[mt], bh[1], bh[3]);
                    mma16816(c[mt][2 * ng + 1], ah[mt], bl[1], bl[3]);
                    mma16816(c[mt][2 * ng + 1], al[mt], bh[1], bh[3]);
                }
            }
        }
        __syncthreads();
    }

    // Epilogue: + bias + emb, write fp16 hi/lo split-head
#pragma unroll
    for (int mt = 0; mt < 2; mt++) {
#pragma unroll
        for (int nt = 0; nt < 8; nt++) {
            const int mloc = wm * 32 + mt * 16 + (lane >> 2);
            const int nloc = wn * 64 + nt * 8 + (lane & 3) * 2;
            const float v00 = c[mt][nt][0] + be[nloc];
            const float v01 = c[mt][nt][1] + be[nloc + 1];
            const float v10 = c[mt][nt][2] + be[nloc];
            const float v11 = c[mt][nt][3] + be[nloc + 1];
            const int N = n0 + nloc;
            const int head = N >> 6;
            const int d = N & 63;
            const int m = m0 + mloc;
            const int bb = m >> 11;
            const int s = m & (S_ - 1);
            const size_t i0 = (((size_t)(bb * NH_ + head)) * S_ + s) * HD_ + d;
            const size_t i1 = (((size_t)(bb * NH_ + head)) * S_ + s + 8) * HD_ + d;
            __half h00 = __float2half_rn(v00), h01 = __float2half_rn(v01);
            __half h10 = __float2half_rn(v10), h11 = __float2half_rn(v11);
            *(__half2*)&ohp[i0] = __halves2half2(h00, h01);
            *(__half2*)&ohp[i1] = __halves2half2(h10, h11);
            *(__half2*)&olp[i0] = __halves2half2(
                __float2half_rn(v00 - __half2float(h00)),
                __float2half_rn(v01 - __half2float(h01)));
            *(__half2*)&olp[i1] = __halves2half2(
                __float2half_rn(v10 - __half2float(h10)),
                __float2half_rn(v11 - __half2float(h11)));
        }
    }
}

// ---------------- flash attention via mma.sync, cp.async 2-stage ------------
// Scores: 3-term fp16 split. PV: 2-term (P_hi x (V_hi + V_lo)); P_lo dropped.
#define KLD   72                 // row = 144 B
#define ATB   (64 * KLD * 2)     // bytes per array per stage (9216)
#define ASTG  (4 * ATB)          // stage stride (36864)
#define ASM   (2 * ASTG + 512)   // + msk[2][64] floats

__global__ __launch_bounds__(256) void attn_mma_kernel(
    const float* __restrict__ mask,   // [B,1,1,S]
    float* __restrict__ out)          // [B,S,H]
{
    extern __shared__ char smem[];
    const uint32_t sbase = smem_u32(smem);

    const int tid = threadIdx.x;
    const int wid = tid >> 5;
    const int lane = tid & 31;
    const int bh = blockIdx.y;
    const int b = bh >> 4;
    const int h = bh & (NH_ - 1);
    const int q0 = blockIdx.x * 128 + wid * 16;

    const int r = lane >> 2;
    const int cc = (lane & 3) * 2;

    // Q fragments (hi/lo) directly from gmem in a-frag layout
    uint32_t qhf[4][4], qlf[4][4];
    {
        const __half* qb_h = g_qh + ((size_t)bh * S_ + q0) * HD_;
        const __half* qb_l = g_ql + ((size_t)bh * S_ + q0) * HD_;
#pragma unroll
        for (int dc = 0; dc < 4; dc++) {
            const int o00 = (r)     * HD_ + dc * 16 + cc;
            const int o10 = (r + 8) * HD_ + dc * 16 + cc;
            qhf[dc][0] = *(const uint32_t*)&qb_h[o00];
            qhf[dc][1] = *(const uint32_t*)&qb_h[o10];
            qhf[dc][2] = *(const uint32_t*)&qb_h[o00 + 8];
            qhf[dc][3] = *(const uint32_t*)&qb_h[o10 + 8];
            qlf[dc][0] = *(const uint32_t*)&qb_l[o00];
            qlf[dc][1] = *(const uint32_t*)&qb_l[o10];
            qlf[dc][2] = *(const uint32_t*)&qb_l[o00 + 8];
            qlf[dc][3] = *(const uint32_t*)&qb_l[o10 + 8];
        }
    }

    float o[8][4];
#pragma unroll
    for (int t = 0; t < 8; t++)
#pragma unroll
        for (int q = 0; q < 4; q++) o[t][q] = 0.f;
    float mrow0 = -1e30f, mrow1 = -1e30f;
    float lrow0 = 0.f, lrow1 = 0.f;

    const uint32_t lmOff = ((lane & 15) * KLD + (lane >> 4) * 8) * 2;

    // gmem->smem mapping: thread -> row tid>>2, chunks tch, tch+1 of 8 per row
    const int trow = tid >> 2;
    const int tch = (tid & 3) * 2;
    const size_t kvrow = ((size_t)bh * S_ + trow) * HD_ + tch * 8;
    const uint32_t rowoff = trow * (KLD * 2) + tch * 16;
    const float* mbase = &mask[(size_t)b * S_];

    auto prefetch = [&](int kt, int stg) {
        const size_t off = kvrow + (size_t)kt * 64 * HD_;
        const uint32_t d = sbase + stg * ASTG + rowoff;
        cp16(d,                g_kh + off);
        cp16(d + 16,           g_kh + off + 8);
        cp16(d + ATB,          g_kl + off);
        cp16(d + ATB + 16,     g_kl + off + 8);
        cp16(d + 2 * ATB,      g_vh + off);
        cp16(d + 2 * ATB + 16, g_vh + off + 8);
        cp16(d + 3 * ATB,      g_vl + off);
        cp16(d + 3 * ATB + 16, g_vl + off + 8);
        if (tid < 16)
            cp16(sbase + 2 * ASTG + stg * 256 + tid * 16,
                 mbase + kt * 64 + tid * 4);
        CP_COMMIT();
    };

    prefetch(0, 0);
    for (int kt = 0; kt < 32; kt++) {
        const int stg = kt & 1;
        if (kt + 1 < 32) { prefetch(kt + 1, stg ^ 1); CP_WAIT1(); }
        else             { CP_WAIT0(); }
        __syncthreads();

        const uint32_t khB = sbase + stg * ASTG + lmOff;
        const uint32_t klB = khB + ATB;
        const uint32_t vhB = khB + 2 * ATB;
        const uint32_t vlB = khB + 3 * ATB;
        const float* msk = (const float*)(smem + 2 * ASTG + stg * 256);

        // ---- scores ----
        float c[8][4];
#pragma unroll
        for (int t = 0; t < 8; t++)
#pragma unroll
            for (int q = 0; q < 4; q++) c[t][q] = 0.f;

#pragma unroll
        for (int kg = 0; kg < 4; kg++) {
#pragma unroll
            for (int dc = 0; dc < 4; dc++) {
                const uint32_t off = (kg * 16 * KLD + dc * 16) * 2;
                uint32_t kf[4], lf[4];
                ldsm4(kf, khB + off);
                ldsm4(lf, klB + off);
                mma16816(c[2 * kg],     qhf[dc], kf[0], kf[2]);
                mma16816(c[2 * kg],     qhf[dc], lf[0], lf[2]);
                mma16816(c[2 * kg],     qlf[dc], kf[0], kf[2]);
                mma16816(c[2 * kg + 1], qhf[dc], kf[1], kf[3]);
                mma16816(c[2 * kg + 1], qhf[dc], lf[1], lf[3]);
                mma16816(c[2 * kg + 1], qlf[dc], kf[1], kf[3]);
            }
        }

        // ---- softmax ----
        float mx0 = mrow0, mx1 = mrow1;
#pragma unroll
        for (int t = 0; t < 8; t++) {
            const float mk0 = msk[8 * t + cc];
            const float mk1 = msk[8 * t + cc + 1];
            c[t][0] = c[t][0] * 0.125f + mk0;
            c[t][1] = c[t][1] * 0.125f + mk1;
            c[t][2] = c[t][2] * 0.125f + mk0;
            c[t][3] = c[t][3] * 0.125f + mk1;
            mx0 = fmaxf(mx0, fmaxf(c[t][0], c[t][1]));
            mx1 = fmaxf(mx1, fmaxf(c[t][2], c[t][3]));
        }
        mx0 = fmaxf(mx0, __shfl_xor_sync(0xffffffffu, mx0, 1));
        mx0 = fmaxf(mx0, __shfl_xor_sync(0xffffffffu, mx0, 2));
        mx1 = fmaxf(mx1, __shfl_xor_sync(0xffffffffu, mx1, 1));
        mx1 = fmaxf(mx1, __shfl_xor_sync(0xffffffffu, mx1, 2));

        const float sc0 = __expf(mrow0 - mx0);
        const float sc1 = __expf(mrow1 - mx1);
        mrow0 = mx0; mrow1 = mx1;
        lrow0 *= sc0; lrow1 *= sc1;
        float rs0 = 0.f, rs1 = 0.f;
#pragma unroll
        for (int t = 0; t < 8; t++) {
            c[t][0] = __expf(c[t][0] - mx0);
            c[t][1] = __expf(c[t][1] - mx0);
            c[t][2] = __expf(c[t][2] - mx1);
            c[t][3] = __expf(c[t][3] - mx1);
            rs0 += c[t][0] + c[t][1];
            rs1 += c[t][2] + c[t][3];
        }
        rs0 += __shfl_xor_sync(0xffffffffu, rs0, 1);
        rs0 += __shfl_xor_sync(0xffffffffu, rs0, 2);
        rs1 += __shfl_xor_sync(0xffffffffu, rs1, 1);
        rs1 += __shfl_xor_sync(0xffffffffu, rs1, 2);
        lrow0 += rs0; lrow1 += rs1;
#pragma unroll
        for (int t = 0; t < 8; t++) {
            o[t][0] *= sc0; o[t][1] *= sc0;
            o[t][2] *= sc1; o[t][3] *= sc1;
        }

        // ---- PV (2-term: P_hi x V_hi + P_hi x V_lo) ----
#pragma unroll
        for (int kg = 0; kg < 4; kg++) {
            uint32_t aph[4];
            {
                __half2 t0 = __floats2half2_rn(c[2 * kg][0], c[2 * kg][1]);
                __half2 t1 = __floats2half2_rn(c[2 * kg][2], c[2 * kg][3]);
                __half2 t2 = __floats2half2_rn(c[2 * kg + 1][0], c[2 * kg + 1][1]);
                __half2 t3 = __floats2half2_rn(c[2 * kg + 1][2], c[2 * kg + 1][3]);
                aph[0] = *(uint32_t*)&t0;
                aph[1] = *(uint32_t*)&t1;
                aph[2] = *(uint32_t*)&t2;
                aph[3] = *(uint32_t*)&t3;
            }
#pragma unroll
            for (int hc = 0; hc < 4; hc++) {
                const uint32_t off = (kg * 16 * KLD + hc * 16) * 2;
                uint32_t vf[4], wf[4];
                ldsm4t(vf, vhB + off);
                ldsm4t(wf, vlB + off);
                mma16816(o[2 * hc],     aph, vf[0], vf[1]);
                mma16816(o[2 * hc],     aph, wf[0], wf[1]);
                mma16816(o[2 * hc + 1], aph, vf[2], vf[3]);
                mma16816(o[2 * hc + 1], aph, wf[2], wf[3]);
            }
        }
        __syncthreads();
    }

    // ---- normalize + write ----
    const float inv0 = 1.0f / lrow0;
    const float inv1 = 1.0f / lrow1;
    const int srow = q0 + r;
    float* ob0 = out + ((size_t)b * S_ + srow) * H_ + h * HD_;
    float* ob1 = out + ((size_t)b * S_ + srow + 8) * H_ + h * HD_;
#pragma unroll
    for (int t = 0; t < 8; t++) {
        float2 w0, w1;
        w0.x = o[t][0] * inv0; w0.y = o[t][1] * inv0;
        w1.x = o[t][2] * inv1; w1.y = o[t][3] * inv1;
        *(float2*)&ob0[8 * t + cc] = w0;
        *(float2*)&ob1[8 * t + cc] = w1;
    }
}

// ---------------------------------------------------------------------------
extern "C" void kernel_launch(void* const* d_in, const int* in_sizes, int n_in,
                              void* d_out, int out_size)
{
    const float* hs   = (const float*)d_in[0];
    const float* mask = (const float*)d_in[1];
    const float* Wq   = (const float*)d_in[2];
    const float* bq   = (const float*)d_in[3];
    const float* Wk   = (const float*)d_in[4];
    const float* bk   = (const float*)d_in[5];
    const float* Wv   = (const float*)d_in[6];
    const float* bv   = (const float*)d_in[7];
    const float* qe   = (const float*)d_in[8];
    const float* ke   = (const float*)d_in[9];
    const float* ve   = (const float*)d_in[10];
    const int*   idx  = (const int*)d_in[11];
    float* out = (float*)d_out;

    static bool attr_done = false;
    if (!attr_done) {
        cudaFuncSetAttribute(qkv_mma_kernel,
                             cudaFuncAttributeMaxDynamicSharedMemorySize, QSM);
        cudaFuncSetAttribute(attn_mma_kernel,
                             cudaFuncAttributeMaxDynamicSharedMemorySize, ASM);
        attr_done = true;
    }

    convert_hs_kernel<<<2048, 256>>>(hs);
    transpose_w_kernel<<<dim3(32, 32, 3), dim3(32, 8)>>>(Wq, Wk, Wv);
    qkv_mma_kernel<<<dim3(8, 64, 3), 256, QSM>>>(bq, bk, bv, qe, ke, ve, idx);
    attn_mma_kernel<<<dim3(16, 64), 256, ASM>>>(mask, out);
}

// round 6
// speedup vs baseline: 3.4256x; 1.1272x over previous
#include <cuda_runtime.h>
#include <cuda_fp16.h>
#include <cstdint>

#define B_   4
#define S_   2048
#define H_   1024
#define NH_  16
#define HD_  64
#define MTOT (B_ * S_)          // 8192
#define HSN  (MTOT * H_)        // 8388608

// ---------------- scratch (device globals; no allocations allowed) ----------
__device__ __half g_hsh[HSN];            // hidden states fp16 hi
__device__ __half g_hsl[HSN];            // hidden states fp16 lo (residual)
__device__ __half g_wth[3 * H_ * H_];    // W^T fp16 hi  (Wt[n*H+k] = W[k*H+n])
__device__ __half g_wtl[3 * H_ * H_];    // W^T fp16 lo
// Q/K/V in split-head layout [B, NH, S, HD], fp16 hi/lo pairs
__device__ __half g_qh[B_ * NH_ * S_ * HD_];
__device__ __half g_ql[B_ * NH_ * S_ * HD_];
__device__ __half g_kh[B_ * NH_ * S_ * HD_];
__device__ __half g_kl[B_ * NH_ * S_ * HD_];
__device__ __half g_vh[B_ * NH_ * S_ * HD_];
__device__ __half g_vl[B_ * NH_ * S_ * HD_];

// ---------------- helpers ---------------------------------------------------
__device__ __forceinline__ uint32_t smem_u32(const void* p) {
    uint32_t a;
    asm("{ .reg .u64 t; cvta.to.shared.u64 t, %1; cvt.u32.u64 %0, t; }"
        : "=r"(a) : "l"(p));
    return a;
}
__device__ __forceinline__ void mma16816(float* c, const uint32_t* a,
                                         uint32_t b0, uint32_t b1) {
    asm volatile(
        "mma.sync.aligned.m16n8k16.row.col.f32.f16.f16.f32 "
        "{%0,%1,%2,%3}, {%4,%5,%6,%7}, {%8,%9}, {%0,%1,%2,%3};"
        : "+f"(c[0]), "+f"(c[1]), "+f"(c[2]), "+f"(c[3])
        : "r"(a[0]), "r"(a[1]), "r"(a[2]), "r"(a[3]), "r"(b0), "r"(b1));
}
__device__ __forceinline__ void ldsm4(uint32_t* r, uint32_t addr) {
    asm volatile("ldmatrix.sync.aligned.m8n8.x4.shared.b16 {%0,%1,%2,%3}, [%4];"
                 : "=r"(r[0]), "=r"(r[1]), "=r"(r[2]), "=r"(r[3]) : "r"(addr));
}
__device__ __forceinline__ void ldsm4t(uint32_t* r, uint32_t addr) {
    asm volatile("ldmatrix.sync.aligned.m8n8.x4.trans.shared.b16 {%0,%1,%2,%3}, [%4];"
                 : "=r"(r[0]), "=r"(r[1]), "=r"(r[2]), "=r"(r[3]) : "r"(addr));
}
__device__ __forceinline__ void cp16(uint32_t dst, const void* src) {
    asm volatile("cp.async.cg.shared.global [%0], [%1], 16;"
                 :: "r"(dst), "l"(src) : "memory");
}
#define CP_COMMIT() asm volatile("cp.async.commit_group;" ::: "memory")
#define CP_WAIT1()  asm volatile("cp.async.wait_group 1;" ::: "memory")
#define CP_WAIT0()  asm volatile("cp.async.wait_group 0;" ::: "memory")

// ---------------- prep kernels ---------------------------------------------
__global__ void convert_hs_kernel(const float* __restrict__ hs) {
    const int n4 = HSN / 4;
    for (int i = blockIdx.x * blockDim.x + threadIdx.x; i < n4;
         i += gridDim.x * blockDim.x) {
        float4 v = ((const float4*)hs)[i];
        __half h0 = __float2half_rn(v.x), h1 = __float2half_rn(v.y);
        __half h2 = __float2half_rn(v.z), h3 = __float2half_rn(v.w);
        __half l0 = __float2half_rn(v.x - __half2float(h0));
        __half l1 = __float2half_rn(v.y - __half2float(h1));
        __half l2 = __float2half_rn(v.z - __half2float(h2));
        __half l3 = __float2half_rn(v.w - __half2float(h3));
        ((__half2*)g_hsh)[2 * i]     = __halves2half2(h0, h1);
        ((__half2*)g_hsh)[2 * i + 1] = __halves2half2(h2, h3);
        ((__half2*)g_hsl)[2 * i]     = __halves2half2(l0, l1);
        ((__half2*)g_hsl)[2 * i + 1] = __halves2half2(l2, l3);
    }
}

__global__ void transpose_w_kernel(const float* __restrict__ Wq,
                                   const float* __restrict__ Wk,
                                   const float* __restrict__ Wv) {
    __shared__ float tile[32][33];
    const int z = blockIdx.z;
    const float* W = (z == 0) ? Wq : (z == 1) ? Wk : Wv;
    __half* oh = g_wth + (size_t)z * H_ * H_;
    __half* ol = g_wtl + (size_t)z * H_ * H_;

    const int x = blockIdx.x * 32 + threadIdx.x;
    const int y0 = blockIdx.y * 32;
#pragma unroll
    for (int j = 0; j < 4; j++)
        tile[threadIdx.y + j * 8][threadIdx.x] =
            W[(size_t)(y0 + threadIdx.y + j * 8) * H_ + x];
    __syncthreads();
#pragma unroll
    for (int j = 0; j < 4; j++) {
        const float v = tile[threadIdx.x][threadIdx.y + j * 8];
        const int n = blockIdx.x * 32 + threadIdx.y + j * 8;
        const int k = y0 + threadIdx.x;
        __half h = __float2half_rn(v);
        oh[(size_t)n * H_ + k] = h;
        ol[(size_t)n * H_ + k] = __float2half_rn(v - __half2float(h));
    }
}

// ---------------- QKV GEMM via mma.sync, cp.async 2-stage -------------------
// CTA: 128x128 tile, 256 thr / 8 warps (4x2), warp tile 32x64, BK=32.
#define GLD   40                 // smem leading dim (halves); row = 80 B
#define QAB   (128 * GLD * 2)    // bytes per array per stage (10240)
#define QSTG  (4 * QAB)          // stage stride (40960)
#define QSM   (2 * QSTG + 512)   // + be[128]

__global__ __launch_bounds__(256, 2) void qkv_mma_kernel(
    const float* __restrict__ bq, const float* __restrict__ bk,
    const float* __restrict__ bv,
    const float* __restrict__ qe, const float* __restrict__ ke,
    const float* __restrict__ ve,
    const int* __restrict__ idxp)
{
    extern __shared__ char smem[];
    float* be = (float*)(smem + 2 * QSTG);

    const int tid = threadIdx.x;
    const int wid = tid >> 5;
    const int lane = tid & 31;
    const int z = blockIdx.z;

    const float* bias;
    const float* emb;
    __half *ohp, *olp;
    if (z == 0)      { bias = bq; emb = qe; ohp = g_qh; olp = g_ql; }
    else if (z == 1) { bias = bk; emb = ke; ohp = g_kh; olp = g_kl; }
    else             { bias = bv; emb = ve; ohp = g_vh; olp = g_vl; }
    emb += (size_t)idxp[0] * H_;

    const int m0 = blockIdx.y * 128;
    const int n0 = blockIdx.x * 128;
    if (tid < 128) be[tid] = bias[n0 + tid] + emb[n0 + tid];

    const int wm = wid & 3;
    const int wn = wid >> 2;

    const int lrow = tid >> 1;
    const int c0 = (tid & 1) * 2;
    const size_t gA = (size_t)(m0 + lrow) * H_;
    const size_t gB = (size_t)(n0 + lrow) * H_;
    const __half* pWh = g_wth + (size_t)z * H_ * H_;
    const __half* pWl = g_wtl + (size_t)z * H_ * H_;

    const uint32_t sbase = smem_u32(smem);
    const uint32_t rowoff = lrow * (GLD * 2) + c0 * 16;

    const uint32_t lmA = ((wm * 32 + (lane & 15)) * GLD + (lane >> 4) * 8) * 2;
    const uint32_t lmB = ((wn * 64 + (lane & 15)) * GLD + (lane >> 4) * 8) * 2;

    float c[2][8][4];
#pragma unroll
    for (int i = 0; i < 2; i++)
#pragma unroll
        for (int j = 0; j < 8; j++)
#pragma unroll
            for (int q = 0; q < 4; q++) c[i][j][q] = 0.f;

    auto prefetch = [&](int kt, int stg) {
        const int k0 = kt * 32;
        const uint32_t d = sbase + stg * QSTG + rowoff;
        cp16(d,            g_hsh + gA + k0 + c0 * 8);
        cp16(d + 16,       g_hsh + gA + k0 + c0 * 8 + 8);
        cp16(d + QAB,      g_hsl + gA + k0 + c0 * 8);
        cp16(d + QAB + 16, g_hsl + gA + k0 + c0 * 8 + 8);
        cp16(d + 2 * QAB,      pWh + gB + k0 + c0 * 8);
        cp16(d + 2 * QAB + 16, pWh + gB + k0 + c0 * 8 + 8);
        cp16(d + 3 * QAB,      pWl + gB + k0 + c0 * 8);
        cp16(d + 3 * QAB + 16, pWl + gB + k0 + c0 * 8 + 8);
        CP_COMMIT();
    };

    prefetch(0, 0);
    for (int kt = 0; kt < 32; kt++) {
        const int stg = kt & 1;
        if (kt + 1 < 32) { prefetch(kt + 1, stg ^ 1); CP_WAIT1(); }
        else             { CP_WAIT0(); }
        __syncthreads();

        const uint32_t aH = sbase + stg * QSTG + lmA;
        const uint32_t aL = aH + QAB;
        const uint32_t bH = sbase + stg * QSTG + 2 * QAB + lmB;
        const uint32_t bL = bH + QAB;

#pragma unroll
        for (int k16 = 0; k16 < 2; k16++) {
            const uint32_t koff = k16 * 32;
            uint32_t ah[2][4], al[2][4];
#pragma unroll
            for (int mt = 0; mt < 2; mt++) {
                ldsm4(ah[mt], aH + mt * (16 * GLD * 2) + koff);
                ldsm4(al[mt], aL + mt * (16 * GLD * 2) + koff);
            }
#pragma unroll
            for (int ng = 0; ng < 4; ng++) {
                uint32_t bh[4], bl[4];
                ldsm4(bh, bH + ng * (16 * GLD * 2) + koff);
                ldsm4(bl, bL + ng * (16 * GLD * 2) + koff);
                // interleaved: same-accumulator chain distance = 4
                mma16816(c[0][2 * ng],     ah[0], bh[0], bh[2]);
                mma16816(c[1][2 * ng],     ah[1], bh[0], bh[2]);
                mma16816(c[0][2 * ng + 1], ah[0], bh[1], bh[3]);
                mma16816(c[1][2 * ng + 1], ah[1], bh[1], bh[3]);
                mma16816(c[0][2 * ng],     ah[0], bl[0], bl[2]);
                mma16816(c[1][2 * ng],     ah[1], bl[0], bl[2]);
                mma16816(c[0][2 * ng + 1], ah[0], bl[1], bl[3]);
                mma16816(c[1][2 * ng + 1], ah[1], bl[1], bl[3]);
                mma16816(c[0][2 * ng],     al[0], bh[0], bh[2]);
                mma16816(c[1][2 * ng],     al[1], bh[0], bh[2]);
                mma16816(c[0][2 * ng + 1], al[0], bh[1], bh[3]);
                mma16816(c[1][2 * ng + 1], al[1], bh[1], bh[3]);
            }
        }
        __syncthreads();
    }

    // Epilogue: + bias + emb, write fp16 hi/lo split-head
#pragma unroll
    for (int mt = 0; mt < 2; mt++) {
#pragma unroll
        for (int nt = 0; nt < 8; nt++) {
            const int mloc = wm * 32 + mt * 16 + (lane >> 2);
            const int nloc = wn * 64 + nt * 8 + (lane & 3) * 2;
            const float v00 = c[mt][nt][0] + be[nloc];
            const float v01 = c[mt][nt][1] + be[nloc + 1];
            const float v10 = c[mt][nt][2] + be[nloc];
            const float v11 = c[mt][nt][3] + be[nloc + 1];
            const int N = n0 + nloc;
            const int head = N >> 6;
            const int d = N & 63;
            const int m = m0 + mloc;
            const int bb = m >> 11;
            const int s = m & (S_ - 1);
            const size_t i0 = (((size_t)(bb * NH_ + head)) * S_ + s) * HD_ + d;
            const size_t i1 = (((size_t)(bb * NH_ + head)) * S_ + s + 8) * HD_ + d;
            __half h00 = __float2half_rn(v00), h01 = __float2half_rn(v01);
            __half h10 = __float2half_rn(v10), h11 = __float2half_rn(v11);
            *(__half2*)&ohp[i0] = __halves2half2(h00, h01);
            *(__half2*)&ohp[i1] = __halves2half2(h10, h11);
            *(__half2*)&olp[i0] = __halves2half2(
                __float2half_rn(v00 - __half2float(h00)),
                __float2half_rn(v01 - __half2float(h01)));
            *(__half2*)&olp[i1] = __halves2half2(
                __float2half_rn(v10 - __half2float(h10)),
                __float2half_rn(v11 - __half2float(h11)));
        }
    }
}

// ---------------- flash attention via mma.sync, cp.async 2-stage ------------
// Scores: 3-term fp16 split. PV: 2-term (P_hi x (V_hi + V_lo)).
#define KLD   72                 // row = 144 B
#define ATB   (64 * KLD * 2)     // bytes per array per stage (9216)
#define ASTG  (4 * ATB)          // stage stride (36864)
#define ASM   (2 * ASTG + 512)   // + msk[2][64] floats

__global__ __launch_bounds__(256, 2) void attn_mma_kernel(
    const float* __restrict__ mask,   // [B,1,1,S]
    float* __restrict__ out)          // [B,S,H]
{
    extern __shared__ char smem[];
    const uint32_t sbase = smem_u32(smem);

    const int tid = threadIdx.x;
    const int wid = tid >> 5;
    const int lane = tid & 31;
    const int bh = blockIdx.y;
    const int b = bh >> 4;
    const int h = bh & (NH_ - 1);
    const int q0 = blockIdx.x * 128 + wid * 16;

    const int r = lane >> 2;
    const int cc = (lane & 3) * 2;

    // Q fragments (hi/lo) directly from gmem in a-frag layout
    uint32_t qhf[4][4], qlf[4][4];
    {
        const __half* qb_h = g_qh + ((size_t)bh * S_ + q0) * HD_;
        const __half* qb_l = g_ql + ((size_t)bh * S_ + q0) * HD_;
#pragma unroll
        for (int dc = 0; dc < 4; dc++) {
            const int o00 = (r)     * HD_ + dc * 16 + cc;
            const int o10 = (r + 8) * HD_ + dc * 16 + cc;
            qhf[dc][0] = *(const uint32_t*)&qb_h[o00];
            qhf[dc][1] = *(const uint32_t*)&qb_h[o10];
            qhf[dc][2] = *(const uint32_t*)&qb_h[o00 + 8];
            qhf[dc][3] = *(const uint32_t*)&qb_h[o10 + 8];
            qlf[dc][0] = *(const uint32_t*)&qb_l[o00];
            qlf[dc][1] = *(const uint32_t*)&qb_l[o10];
            qlf[dc][2] = *(const uint32_t*)&qb_l[o00 + 8];
            qlf[dc][3] = *(const uint32_t*)&qb_l[o10 + 8];
        }
    }

    float o[8][4];
#pragma unroll
    for (int t = 0; t < 8; t++)
#pragma unroll
        for (int q = 0; q < 4; q++) o[t][q] = 0.f;
    float mrow0 = -1e30f, mrow1 = -1e30f;
    float lrow0 = 0.f, lrow1 = 0.f;

    const uint32_t lmOff = ((lane & 15) * KLD + (lane >> 4) * 8) * 2;

    const int trow = tid >> 2;
    const int tch = (tid & 3) * 2;
    const size_t kvrow = ((size_t)bh * S_ + trow) * HD_ + tch * 8;
    const uint32_t rowoff = trow * (KLD * 2) + tch * 16;
    const float* mbase = &mask[(size_t)b * S_];

    auto prefetch = [&](int kt, int stg) {
        const size_t off = kvrow + (size_t)kt * 64 * HD_;
        const uint32_t d = sbase + stg * ASTG + rowoff;
        cp16(d,                g_kh + off);
        cp16(d + 16,           g_kh + off + 8);
        cp16(d + ATB,          g_kl + off);
        cp16(d + ATB + 16,     g_kl + off + 8);
        cp16(d + 2 * ATB,      g_vh + off);
        cp16(d + 2 * ATB + 16, g_vh + off + 8);
        cp16(d + 3 * ATB,      g_vl + off);
        cp16(d + 3 * ATB + 16, g_vl + off + 8);
        if (tid < 16)
            cp16(sbase + 2 * ASTG + stg * 256 + tid * 16,
                 mbase + kt * 64 + tid * 4);
        CP_COMMIT();
    };

    prefetch(0, 0);
    for (int kt = 0; kt < 32; kt++) {
        const int stg = kt & 1;
        if (kt + 1 < 32) { prefetch(kt + 1, stg ^ 1); CP_WAIT1(); }
        else             { CP_WAIT0(); }
        __syncthreads();

        const uint32_t khB = sbase + stg * ASTG + lmOff;
        const uint32_t klB = khB + ATB;
        const uint32_t vhB = khB + 2 * ATB;
        const uint32_t vlB = khB + 3 * ATB;
        const float* msk = (const float*)(smem + 2 * ASTG + stg * 256);

        // ---- scores (interleaved accumulators) ----
        float c[8][4];
#pragma unroll
        for (int t = 0; t < 8; t++)
#pragma unroll
            for (int q = 0; q < 4; q++) c[t][q] = 0.f;

#pragma unroll
        for (int kg = 0; kg < 4; kg++) {
#pragma unroll
            for (int dc = 0; dc < 4; dc++) {
                const uint32_t off = (kg * 16 * KLD + dc * 16) * 2;
                uint32_t kf[4], lf[4];
                ldsm4(kf, khB + off);
                ldsm4(lf, klB + off);
                mma16816(c[2 * kg],     qhf[dc], kf[0], kf[2]);
                mma16816(c[2 * kg + 1], qhf[dc], kf[1], kf[3]);
                mma16816(c[2 * kg],     qhf[dc], lf[0], lf[2]);
                mma16816(c[2 * kg + 1], qhf[dc], lf[1], lf[3]);
                mma16816(c[2 * kg],     qlf[dc], kf[0], kf[2]);
                mma16816(c[2 * kg + 1], qlf[dc], kf[1], kf[3]);
            }
        }

        // ---- softmax ----
        float mx0 = mrow0, mx1 = mrow1;
#pragma unroll
        for (int t = 0; t < 8; t++) {
            const float mk0 = msk[8 * t + cc];
            const float mk1 = msk[8 * t + cc + 1];
            c[t][0] = c[t][0] * 0.125f + mk0;
            c[t][1] = c[t][1] * 0.125f + mk1;
            c[t][2] = c[t][2] * 0.125f + mk0;
            c[t][3] = c[t][3] * 0.125f + mk1;
            mx0 = fmaxf(mx0, fmaxf(c[t][0], c[t][1]));
            mx1 = fmaxf(mx1, fmaxf(c[t][2], c[t][3]));
        }
        mx0 = fmaxf(mx0, __shfl_xor_sync(0xffffffffu, mx0, 1));
        mx0 = fmaxf(mx0, __shfl_xor_sync(0xffffffffu, mx0, 2));
        mx1 = fmaxf(mx1, __shfl_xor_sync(0xffffffffu, mx1, 1));
        mx1 = fmaxf(mx1, __shfl_xor_sync(0xffffffffu, mx1, 2));

        const float sc0 = __expf(mrow0 - mx0);
        const float sc1 = __expf(mrow1 - mx1);
        mrow0 = mx0; mrow1 = mx1;
        lrow0 *= sc0; lrow1 *= sc1;
        float rs0 = 0.f, rs1 = 0.f;
#pragma unroll
        for (int t = 0; t < 8; t++) {
            c[t][0] = __expf(c[t][0] - mx0);
            c[t][1] = __expf(c[t][1] - mx0);
            c[t][2] = __expf(c[t][2] - mx1);
            c[t][3] = __expf(c[t][3] - mx1);
            rs0 += c[t][0] + c[t][1];
            rs1 += c[t][2] + c[t][3];
        }
        rs0 += __shfl_xor_sync(0xffffffffu, rs0, 1);
        rs0 += __shfl_xor_sync(0xffffffffu, rs0, 2);
        rs1 += __shfl_xor_sync(0xffffffffu, rs1, 1);
        rs1 += __shfl_xor_sync(0xffffffffu, rs1, 2);
        lrow0 += rs0; lrow1 += rs1;
#pragma unroll
        for (int t = 0; t < 8; t++) {
            o[t][0] *= sc0; o[t][1] *= sc0;
            o[t][2] *= sc1; o[t][3] *= sc1;
        }

        // ---- PV (2-term, interleaved accumulators) ----
#pragma unroll
        for (int kg = 0; kg < 4; kg++) {
            uint32_t aph[4];
            {
                __half2 t0 = __floats2half2_rn(c[2 * kg][0], c[2 * kg][1]);
                __half2 t1 = __floats2half2_rn(c[2 * kg][2], c[2 * kg][3]);
                __half2 t2 = __floats2half2_rn(c[2 * kg + 1][0], c[2 * kg + 1][1]);
                __half2 t3 = __floats2half2_rn(c[2 * kg + 1][2], c[2 * kg + 1][3]);
                aph[0] = *(uint32_t*)&t0;
                aph[1] = *(uint32_t*)&t1;
                aph[2] = *(uint32_t*)&t2;
                aph[3] = *(uint32_t*)&t3;
            }
#pragma unroll
            for (int hc = 0; hc < 4; hc++) {
                const uint32_t off = (kg * 16 * KLD + hc * 16) * 2;
                uint32_t vf[4], wf[4];
                ldsm4t(vf, vhB + off);
                ldsm4t(wf, vlB + off);
                mma16816(o[2 * hc],     aph, vf[0], vf[1]);
                mma16816(o[2 * hc + 1], aph, vf[2], vf[3]);
                mma16816(o[2 * hc],     aph, wf[0], wf[1]);
                mma16816(o[2 * hc + 1], aph, wf[2], wf[3]);
            }
        }
        __syncthreads();
    }

    // ---- normalize + write ----
    const float inv0 = 1.0f / lrow0;
    const float inv1 = 1.0f / lrow1;
    const int srow = q0 + r;
    float* ob0 = out + ((size_t)b * S_ + srow) * H_ + h * HD_;
    float* ob1 = out + ((size_t)b * S_ + srow + 8) * H_ + h * HD_;
#pragma unroll
    for (int t = 0; t < 8; t++) {
        float2 w0, w1;
        w0.x = o[t][0] * inv0; w0.y = o[t][1] * inv0;
        w1.x = o[t][2] * inv1; w1.y = o[t][3] * inv1;
        *(float2*)&ob0[8 * t + cc] = w0;
        *(float2*)&ob1[8 * t + cc] = w1;
    }
}

// ---------------------------------------------------------------------------
extern "C" void kernel_launch(void* const* d_in, const int* in_sizes, int n_in,
                              void* d_out, int out_size)
{
    const float* hs   = (const float*)d_in[0];
    const float* mask = (const float*)d_in[1];
    const float* Wq   = (const float*)d_in[2];
    const float* bq   = (const float*)d_in[3];
    const float* Wk   = (const float*)d_in[4];
    const float* bk   = (const float*)d_in[5];
    const float* Wv   = (const float*)d_in[6];
    const float* bv   = (const float*)d_in[7];
    const float* qe   = (const float*)d_in[8];
    const float* ke   = (const float*)d_in[9];
    const float* ve   = (const float*)d_in[10];
    const int*   idx  = (const int*)d_in[11];
    float* out = (float*)d_out;

    static bool attr_done = false;
    if (!attr_done) {
        cudaFuncSetAttribute(qkv_mma_kernel,
                             cudaFuncAttributeMaxDynamicSharedMemorySize, QSM);
        cudaFuncSetAttribute(attn_mma_kernel,
                             cudaFuncAttributeMaxDynamicSharedMemorySize, ASM);
        attr_done = true;
    }

    convert_hs_kernel<<<2048, 256>>>(hs);
    transpose_w_kernel<<<dim3(32, 32, 3), dim3(32, 8)>>>(Wq, Wk, Wv);
    qkv_mma_kernel<<<dim3(8, 64, 3), 256, QSM>>>(bq, bk, bv, qe, ke, ve, idx);
    attn_mma_kernel<<<dim3(16, 64), 256, ASM>>>(mask, out);
}